// round 8
// baseline (speedup 1.0000x reference)
#include <cuda_runtime.h>
#include <cuda_bf16.h>
#include <cstdint>

#define N_NODES 50000
#define N_EDGES 800000
#define D_IN 128
#define D_HID 256
#define D_OUT 128

// ---------------- scratch (static device arrays; no allocation) ----------------
__device__ __nv_bfloat16 g_a1h[(size_t)N_NODES * D_IN];    // agg1 hi   12.8 MB
__device__ __nv_bfloat16 g_a1l[(size_t)N_NODES * D_IN];    // agg1 lo
__device__ __nv_bfloat16 g_h1h[(size_t)N_NODES * D_HID];   // h1 hi     25.6 MB
__device__ __nv_bfloat16 g_h1l[(size_t)N_NODES * D_HID];   // h1 lo
__device__ float         g_t2[(size_t)N_NODES * D_OUT];    // 25.6 MB
__device__ __nv_bfloat16 g_w1th[D_HID * D_IN], g_w1tl[D_HID * D_IN];
__device__ __nv_bfloat16 g_w2th[D_OUT * D_HID], g_w2tl[D_OUT * D_HID];
__device__ int g_deg[N_NODES];
__device__ int g_off[N_NODES + 1];
__device__ int g_rank[N_EDGES];
__device__ int g_csr_src[N_EDGES];   // src node id  (layer-2 gather index)
__device__ int g_csr_c[N_EDGES];     // cncpt[src]   (layer-1 gather index)

// ================= small helpers =================
__device__ __forceinline__ uint32_t smem_u32(const void* p) {
    uint32_t a;
    asm("{ .reg .u64 t; cvta.to.shared.u64 t, %1; cvt.u32.u64 %0, t; }" : "=r"(a) : "l"(p));
    return a;
}

// split fp32 pair -> (hi bf16x2, lo bf16x2); low half of the b32 = first elem
__device__ __forceinline__ void split2(float a0, float a1, uint32_t& hi, uint32_t& lo) {
    asm("cvt.rn.bf16x2.f32 %0, %1, %2;" : "=r"(hi) : "f"(a1), "f"(a0));
    float h0 = __uint_as_float(hi << 16);
    float h1 = __uint_as_float(hi & 0xFFFF0000u);
    float l0 = a0 - h0, l1 = a1 - h1;
    asm("cvt.rn.bf16x2.f32 %0, %1, %2;" : "=r"(lo) : "f"(l1), "f"(l0));
}

__device__ __forceinline__ void ldsm_x4(uint32_t* r, uint32_t addr) {
    asm volatile("ldmatrix.sync.aligned.m8n8.x4.shared.b16 {%0,%1,%2,%3}, [%4];"
                 : "=r"(r[0]), "=r"(r[1]), "=r"(r[2]), "=r"(r[3]) : "r"(addr));
}

__device__ __forceinline__ void mma16816(float* d, const uint32_t* a, const uint32_t* b) {
    asm volatile("mma.sync.aligned.m16n8k16.row.col.f32.bf16.bf16.f32 "
                 "{%0,%1,%2,%3}, {%4,%5,%6,%7}, {%8,%9}, {%0,%1,%2,%3};"
                 : "+f"(d[0]), "+f"(d[1]), "+f"(d[2]), "+f"(d[3])
                 : "r"(a[0]), "r"(a[1]), "r"(a[2]), "r"(a[3]), "r"(b[0]), "r"(b[1]));
}

__device__ __forceinline__ void cp_async16(uint32_t dst, const void* src, int size) {
    asm volatile("cp.async.cg.shared.global [%0], [%1], 16, %2;"
                 :: "r"(dst), "l"(src), "r"(size) : "memory");
}

// swizzled smem byte offset within a plane: row stride 64B, chunk16 XOR (row>>1)&3
__device__ __forceinline__ uint32_t swz(int row, int chunk) {
    return (uint32_t)(row * 64 + ((chunk ^ ((row >> 1) & 3)) << 4));
}

// ================= CSR build =================
__global__ void zero_deg() {
    int i = blockIdx.x * blockDim.x + threadIdx.x;
    if (i < N_NODES) g_deg[i] = 0;
}
// histogram (2 edges/thread); records each edge's within-bucket rank
__global__ __launch_bounds__(256) void hist_dst(const int2* __restrict__ dst2) {
    int i = blockIdx.x * blockDim.x + threadIdx.x;
    if (i >= N_EDGES / 2) return;
    int2 d = dst2[i];
    int r0 = atomicAdd(&g_deg[d.x], 1);
    int r1 = atomicAdd(&g_deg[d.y], 1);
    *(int2*)&g_rank[2 * i] = make_int2(r0, r1);
}
__global__ __launch_bounds__(1024) void scan_deg() {
    __shared__ int sums[1024];
    const int CHUNK = (N_NODES + 1023) / 1024;
    int t = threadIdx.x;
    int lo = t * CHUNK;
    int hi = min(lo + CHUNK, N_NODES);
    int s = 0;
    for (int i = lo; i < hi; i++) s += g_deg[i];
    sums[t] = s;
    __syncthreads();
    for (int d = 1; d < 1024; d <<= 1) {
        int v = (t >= d) ? sums[t - d] : 0;
        __syncthreads();
        sums[t] += v;
        __syncthreads();
    }
    int running = sums[t] - s;
    for (int i = lo; i < hi; i++) {
        g_off[i] = running;
        running += g_deg[i];
    }
    if (t == 1023) g_off[N_NODES] = sums[1023];
}
// non-atomic scatter (2 edges/thread); also pre-composes cncpt[src] for layer-1
__global__ __launch_bounds__(256) void scatter_edges(
    const int2* __restrict__ src2, const int2* __restrict__ dst2,
    const int* __restrict__ cncpt)
{
    int i = blockIdx.x * blockDim.x + threadIdx.x;
    if (i >= N_EDGES / 2) return;
    int2 s = src2[i];
    int2 d = dst2[i];
    int2 r = *(const int2*)&g_rank[2 * i];
    int p0 = g_off[d.x] + r.x;
    int p1 = g_off[d.y] + r.y;
    int c0 = cncpt[s.x];
    int c1 = cncpt[s.y];
    g_csr_src[p0] = s.x;
    g_csr_src[p1] = s.y;
    g_csr_c[p0] = c0;
    g_csr_c[p1] = c1;
}

// ================= CSR aggregation: warp per node, no atomics =================
template<bool EPI, bool SPLIT>
__global__ __launch_bounds__(256) void agg_csr(
    const int* __restrict__ idx, const float4* __restrict__ rows,
    const float* __restrict__ bias, float4* __restrict__ outf,
    __nv_bfloat16* __restrict__ oh, __nv_bfloat16* __restrict__ ol)
{
    int w = (blockIdx.x * blockDim.x + threadIdx.x) >> 5;
    if (w >= N_NODES) return;
    int lane = threadIdx.x & 31;
    int beg = g_off[w], end = g_off[w + 1];

    float4 acc = make_float4(0.f, 0.f, 0.f, 0.f);
    int j = beg;
    for (; j + 8 <= end; j += 8) {
        int s[8];
#pragma unroll
        for (int q = 0; q < 8; q++) s[q] = idx[j + q];
        float4 v[8];
#pragma unroll
        for (int q = 0; q < 8; q++) v[q] = rows[(size_t)s[q] * 32 + lane];
#pragma unroll
        for (int q = 0; q < 8; q++) {
            acc.x += v[q].x; acc.y += v[q].y; acc.z += v[q].z; acc.w += v[q].w;
        }
    }
    for (; j < end; j++) {
        float4 v = rows[(size_t)idx[j] * 32 + lane];
        acc.x += v.x; acc.y += v.y; acc.z += v.z; acc.w += v.w;
    }
    if (EPI) {
        float4 b = ((const float4*)bias)[lane];
        acc.x = fmaxf(acc.x + b.x, 0.f);
        acc.y = fmaxf(acc.y + b.y, 0.f);
        acc.z = fmaxf(acc.z + b.z, 0.f);
        acc.w = fmaxf(acc.w + b.w, 0.f);
    }
    if (SPLIT) {
        uint32_t h0, l0, h1, l1;
        split2(acc.x, acc.y, h0, l0);
        split2(acc.z, acc.w, h1, l1);
        size_t off = (size_t)w * 128 + lane * 4;
        *(uint2*)(oh + off) = make_uint2(h0, h1);
        *(uint2*)(ol + off) = make_uint2(l0, l1);
    } else {
        outf[(size_t)w * 32 + lane] = acc;
    }
}

// ================= fused weight transpose + split (one launch) =================
__global__ void prep_weights(const float* __restrict__ W1, const float* __restrict__ W2) {
    int i = blockIdx.x * blockDim.x + threadIdx.x;
    if (i < D_HID * D_IN) {                  // W1^T [256][128]
        int n = i / D_IN, k = i % D_IN;
        float v = W1[(size_t)k * D_HID + n];
        __nv_bfloat16 h = __float2bfloat16_rn(v);
        g_w1th[i] = h;
        g_w1tl[i] = __float2bfloat16_rn(v - __bfloat162float(h));
    } else if (i < D_HID * D_IN + D_OUT * D_HID) {   // W2^T [128][256]
        int j = i - D_HID * D_IN;
        int n = j / D_HID, k = j % D_HID;
        float v = W2[(size_t)k * D_OUT + n];
        __nv_bfloat16 h = __float2bfloat16_rn(v);
        g_w2th[j] = h;
        g_w2tl[j] = __float2bfloat16_rn(v - __bfloat162float(h));
    }
}

// ================= HMMA split-bf16 GEMM, cp.async double-buffered =================
// C[M,NN] = (Ah+Al)[M,KK] @ (Bh+Bl)[NN,KK]^T via 3 products, fp32 accumulate.
// B fragments loaded on demand per j-pair (low register pressure -> no spills
// at 2 CTAs/SM). MODE 0: fp32 out. MODE 1: bias+relu, split bf16 out.
template<int BM, int NN, int KK, int MODE>
__global__ __launch_bounds__(256, 2) void hmma_gemm(
    const __nv_bfloat16* __restrict__ Ah, const __nv_bfloat16* __restrict__ Al,
    const __nv_bfloat16* __restrict__ Bh, const __nv_bfloat16* __restrict__ Bl,
    const float* __restrict__ bias, float* __restrict__ Cf,
    __nv_bfloat16* __restrict__ Ch, __nv_bfloat16* __restrict__ Cl, int M)
{
    constexpr int WMW = (BM == 128) ? 4 : 2;   // warps along M
    constexpr int WNW = 8 / WMW;               // warps along N
    constexpr int NW  = 128 / WNW;             // warp n-width (64 / 32)
    constexpr int NT  = NW / 8;                // n-tiles per warp (8 / 4)
    constexpr int APLANE_B = BM * 64;
    constexpr int BPLANE_B = 128 * 64;
    constexpr int STAGE_B  = 2 * APLANE_B + 2 * BPLANE_B;
    constexpr int ITERS    = (2 * BM + 256) * 4 / 256;   // 16B chunks per thread
    extern __shared__ __align__(16) char smem[];         // [2][STAGE_B]

    const int tid  = threadIdx.x;
    const int wid  = tid >> 5;
    const int lane = tid & 31;
    const int wm   = wid % WMW;
    const int wn   = wid / WMW;
    const int blockM = blockIdx.y * BM;
    const int blockN = blockIdx.x * 128;

    const uint32_t sb0 = smem_u32(smem);

    const int a_row = wm * 32 + (lane & 15);
    const int a_chk = lane >> 4;
    const int b_row = wn * NW + ((lane >> 4) << 3) + (lane & 7);
    const int b_chk = (lane >> 3) & 1;

    float acc[2][NT][4];
#pragma unroll
    for (int mt = 0; mt < 2; mt++)
#pragma unroll
        for (int j = 0; j < NT; j++)
#pragma unroll
            for (int q = 0; q < 4; q++) acc[mt][j][q] = 0.f;

    auto load_stage = [&](int s, int kc) {
        uint32_t sb = sb0 + (uint32_t)s * STAGE_B;
#pragma unroll
        for (int i = 0; i < ITERS; i++) {
            int g = i * 256 + tid;
            const __nv_bfloat16* src;
            uint32_t dst;
            int size = 16;
            if (g < 2 * BM * 4) {
                int p   = g >= BM * 4;              // 0=Ah, 1=Al
                int idx = g - p * BM * 4;
                int row = idx >> 2, c = idx & 3;
                int gm = blockM + row;
                int cm = gm < M ? gm : 0;
                if (gm >= M) size = 0;
                src = (p ? Al : Ah) + (size_t)cm * KK + kc + c * 8;
                dst = sb + (uint32_t)(p * APLANE_B) + swz(row, c);
            } else {
                int gb  = g - 8 * BM;
                int p   = gb >> 9;                  // 0=Bh, 1=Bl
                int idx = gb & 511;
                int row = idx >> 2, c = idx & 3;
                src = (p ? Bl : Bh) + (size_t)(blockN + row) * KK + kc + c * 8;
                dst = sb + (uint32_t)(2 * APLANE_B + p * BPLANE_B) + swz(row, c);
            }
            cp_async16(dst, src, size);
        }
        asm volatile("cp.async.commit_group;" ::: "memory");
    };

    constexpr int NC = KK / 32;
    load_stage(0, 0);

    for (int c = 0; c < NC; c++) {
        if (c + 1 < NC) {
            load_stage((c + 1) & 1, (c + 1) * 32);
            asm volatile("cp.async.wait_group 1;" ::: "memory");
        } else {
            asm volatile("cp.async.wait_group 0;" ::: "memory");
        }
        __syncthreads();

        const uint32_t base = sb0 + (uint32_t)(c & 1) * STAGE_B;
#pragma unroll
        for (int kh = 0; kh < 2; kh++) {
            uint32_t ah[2][4], al[2][4];
#pragma unroll
            for (int mt = 0; mt < 2; mt++) {
                uint32_t off = swz(a_row + mt * 16, kh * 2 + a_chk);
                ldsm_x4(ah[mt], base + off);
                ldsm_x4(al[mt], base + APLANE_B + off);
            }
            // B fragments on demand per j-pair: 12 MMAs per pair,
            // same-acc reuse distance 4 (latency hidden by 16 warps/SM).
#pragma unroll
            for (int jj = 0; jj < NT / 2; jj++) {
                uint32_t off = 2 * APLANE_B + swz(b_row + jj * 16, kh * 2 + b_chk);
                uint32_t tb[4], tl[4];
                ldsm_x4(tb, base + off);
                ldsm_x4(tl, base + BPLANE_B + off);
                const int j0 = 2 * jj, j1 = 2 * jj + 1;
                mma16816(acc[0][j0], ah[0], tb + 0);
                mma16816(acc[1][j0], ah[1], tb + 0);
                mma16816(acc[0][j1], ah[0], tb + 2);
                mma16816(acc[1][j1], ah[1], tb + 2);
                mma16816(acc[0][j0], ah[0], tl + 0);
                mma16816(acc[1][j0], ah[1], tl + 0);
                mma16816(acc[0][j1], ah[0], tl + 2);
                mma16816(acc[1][j1], ah[1], tl + 2);
                mma16816(acc[0][j0], al[0], tb + 0);
                mma16816(acc[1][j0], al[1], tb + 0);
                mma16816(acc[0][j1], al[0], tb + 2);
                mma16816(acc[1][j1], al[1], tb + 2);
            }
        }
        __syncthreads();
    }

    // ---- epilogue from C fragments ----
    const int m_base = blockM + wm * 32 + (lane >> 2);
    const int n_base = blockN + wn * NW + 2 * (lane & 3);
#pragma unroll
    for (int mt = 0; mt < 2; mt++) {
#pragma unroll
        for (int j = 0; j < NT; j++) {
            int n = n_base + 8 * j;
            float2 v0 = make_float2(acc[mt][j][0], acc[mt][j][1]);
            float2 v1 = make_float2(acc[mt][j][2], acc[mt][j][3]);
            int m = m_base + mt * 16;
            if (MODE == 1) {
                float bb0 = bias[n], bb1 = bias[n + 1];
                v0.x = fmaxf(v0.x + bb0, 0.f); v0.y = fmaxf(v0.y + bb1, 0.f);
                v1.x = fmaxf(v1.x + bb0, 0.f); v1.y = fmaxf(v1.y + bb1, 0.f);
                uint32_t h, l;
                if (m < M) {
                    split2(v0.x, v0.y, h, l);
                    *(uint32_t*)(Ch + (size_t)m * NN + n) = h;
                    *(uint32_t*)(Cl + (size_t)m * NN + n) = l;
                }
                if (m + 8 < M) {
                    split2(v1.x, v1.y, h, l);
                    *(uint32_t*)(Ch + (size_t)(m + 8) * NN + n) = h;
                    *(uint32_t*)(Cl + (size_t)(m + 8) * NN + n) = l;
                }
            } else {
                if (m < M)     *(float2*)(Cf + (size_t)m * NN + n)       = v0;
                if (m + 8 < M) *(float2*)(Cf + (size_t)(m + 8) * NN + n) = v1;
            }
        }
    }
}

// ---------------- launch ----------------
extern "C" void kernel_launch(void* const* d_in, const int* in_sizes, int n_in,
                              void* d_out, int out_size) {
    const int*   cncpt = (const int*)d_in[0];
    const int*   src   = (const int*)d_in[1];
    const int*   dst   = (const int*)d_in[2];
    const float* emb   = (const float*)d_in[3];
    const float* W1    = (const float*)d_in[4];
    const float* b1    = (const float*)d_in[5];
    const float* W2    = (const float*)d_in[6];
    const float* b2    = (const float*)d_in[7];
    float* out = (float*)d_out;

    __nv_bfloat16 *a1h, *a1l, *h1h, *h1l, *w1th, *w1tl, *w2th, *w2tl;
    float *t2;
    int *csr_src, *csr_c;
    cudaGetSymbolAddress((void**)&a1h,  g_a1h);
    cudaGetSymbolAddress((void**)&a1l,  g_a1l);
    cudaGetSymbolAddress((void**)&h1h,  g_h1h);
    cudaGetSymbolAddress((void**)&h1l,  g_h1l);
    cudaGetSymbolAddress((void**)&t2,   g_t2);
    cudaGetSymbolAddress((void**)&w1th, g_w1th);
    cudaGetSymbolAddress((void**)&w1tl, g_w1tl);
    cudaGetSymbolAddress((void**)&w2th, g_w2th);
    cudaGetSymbolAddress((void**)&w2tl, g_w2tl);
    cudaGetSymbolAddress((void**)&csr_src, g_csr_src);
    cudaGetSymbolAddress((void**)&csr_c,   g_csr_c);

    const int SMEM1 = 2 * (2 * 128 * 64 + 2 * 128 * 64);   // 65536 B (BM=128)
    const int SMEM2 = 2 * (2 * 64 * 64 + 2 * 128 * 64);    // 49152 B (BM=64)
    cudaFuncSetAttribute(hmma_gemm<128, D_HID, D_IN, 1>,
                         cudaFuncAttributeMaxDynamicSharedMemorySize, SMEM1);
    cudaFuncSetAttribute(hmma_gemm<64, D_OUT, D_HID, 0>,
                         cudaFuncAttributeMaxDynamicSharedMemorySize, SMEM2);

    // ---- build CSR (by dst) ----
    zero_deg<<<(N_NODES + 255) / 256, 256>>>();
    hist_dst<<<(N_EDGES / 2 + 255) / 256, 256>>>((const int2*)dst);
    scan_deg<<<1, 1024>>>();
    scatter_edges<<<(N_EDGES / 2 + 255) / 256, 256>>>(
        (const int2*)src, (const int2*)dst, cncpt);

    // ---- weight transpose + pre-split (one tiny launch) ----
    prep_weights<<<(D_HID * D_IN + D_OUT * D_HID + 255) / 256, 256>>>(W1, W2);

    const int agg_blocks = (N_NODES * 32 + 255) / 256;

    // layer 1 aggregation (index = pre-composed concept ids) -> split bf16 planes
    agg_csr<false, true><<<agg_blocks, 256>>>(
        csr_c, (const float4*)emb, nullptr, nullptr, a1h, a1l);

    // h1 = relu(agg1 @ W1 + b1) -> split bf16 planes  (tiles 128x128)
    hmma_gemm<128, D_HID, D_IN, 1><<<dim3(D_HID / 128, (N_NODES + 127) / 128), 256, SMEM1>>>(
        a1h, a1l, w1th, w1tl, b1, nullptr, h1h, h1l, N_NODES);

    // t2 = h1 @ W2 (GEMM commuted before aggregation) -> fp32  (tiles 64x128)
    hmma_gemm<64, D_OUT, D_HID, 0><<<dim3(1, (N_NODES + 63) / 64), 256, SMEM2>>>(
        h1h, h1l, w2th, w2tl, nullptr, t2, nullptr, nullptr, N_NODES);

    // layer 2 aggregation + bias + relu into d_out
    agg_csr<true, false><<<agg_blocks, 256>>>(
        csr_src, (const float4*)t2, b2, (float4*)out, nullptr, nullptr);
}